// round 1
// baseline (speedup 1.0000x reference)
#include <cuda_runtime.h>
#include <cuda_bf16.h>
#include <math.h>

// Problem constants
#define Bb   8
#define Nn   1024
#define Cc   768
#define Hh   8
#define HD   96
#define DFF  3072
#define NT_  (Bb * Nn)          // 8192 tokens

// ---------------------------------------------------------------------------
// Scratch (device globals — no allocation allowed)
// ---------------------------------------------------------------------------
__device__ float g_q[(size_t)Bb * Hh * Nn * HD];          // [b][h][n][d]  ~25 MB
__device__ float g_attn[(size_t)Bb * Hh * Nn * Nn];       // [b][h][n][m]  256 MB
__device__ float g_x[(size_t)NT_ * Cc];                   // attn-out / ffn2-out
__device__ float g_y[(size_t)NT_ * Cc];                   // post-LN1
__device__ float g_h[(size_t)NT_ * DFF];                  // ffn hidden    100 MB

// ---------------------------------------------------------------------------
// Kernel 1: per-patch 3x3 conv (SAME, NHWC, HWIO), q=k=v, write [b][h][n][d]
// ---------------------------------------------------------------------------
__global__ void qconv_kernel(const float* __restrict__ x, const float* __restrict__ w)
{
    __shared__ float s_in[768];
    __shared__ float s_w[81];
    int bn = blockIdx.x;                 // 0..8191
    int b  = bn >> 10, n = bn & 1023;
    int t  = threadIdx.x;                // 256
    const float* xin = x + (size_t)bn * 768;
    s_in[t]       = xin[t];
    s_in[t + 256] = xin[t + 256];
    s_in[t + 512] = xin[t + 512];
    if (t < 81) s_w[t] = w[t];
    __syncthreads();

    int r = t >> 4, c = t & 15;
    float acc0 = 0.f, acc1 = 0.f, acc2 = 0.f;
    #pragma unroll
    for (int kh = 0; kh < 3; kh++) {
        int rr = r + kh - 1;
        if (rr < 0 || rr > 15) continue;
        #pragma unroll
        for (int kw = 0; kw < 3; kw++) {
            int cc = c + kw - 1;
            if (cc < 0 || cc > 15) continue;
            const float* wp = s_w + (kh * 3 + kw) * 9;   // [ci][co]
            int ip = (rr * 16 + cc) * 3;
            #pragma unroll
            for (int ci = 0; ci < 3; ci++) {
                float v = s_in[ip + ci];
                acc0 += v * wp[ci * 3 + 0];
                acc1 += v * wp[ci * 3 + 1];
                acc2 += v * wp[ci * 3 + 2];
            }
        }
    }
    float accs[3] = {acc0, acc1, acc2};
    #pragma unroll
    for (int co = 0; co < 3; co++) {
        int cidx = t * 3 + co;              // channel in [0,768)
        int h = cidx / HD, d = cidx % HD;
        g_q[(((size_t)b * Hh + h) * Nn + n) * HD + d] = accs[co];
    }
}

// ---------------------------------------------------------------------------
// Generic tiled fp32 GEMM.
//   C = A(MxK, lda) * op(B) (+ epilogue)   op(B)=B (NN, KxN ldb) or B^T (NT, NxK ldb)
// MODE 0: store acc*scale
// MODE 1: store acc + bias[col] + res[row*ldres + col]
// MODE 2: store gelu_exact(acc + bias[col])
// MODE 3: store acc at special attn-output layout (bz = b*8+h, col offset h*96)
// ---------------------------------------------------------------------------
template<int BM, int BN, int BK, int TM, int TN, bool TRANSB, int MODE>
__global__ __launch_bounds__(256)
void gemm_kernel(const float* __restrict__ A, const float* __restrict__ Bm,
                 float* __restrict__ Cm,
                 int M, int Nc, int K, int lda, int ldb, int ldc,
                 size_t strideA, size_t strideB, size_t strideC,
                 const float* __restrict__ bias, const float* __restrict__ res,
                 int ldres, float scale)
{
    __shared__ float As[BK][BM];
    __shared__ float Bs[BK][BN];

    int bz = blockIdx.z;
    A  += strideA * bz;
    Bm += strideB * bz;
    Cm += strideC * bz;

    int m0 = blockIdx.y * BM;
    int n0 = blockIdx.x * BN;
    int t  = threadIdx.x;                    // 256
    constexpr int TX = BN / TN;              // 16
    int tx = t % TX, ty = t / TX;

    float acc[TM][TN];
    #pragma unroll
    for (int i = 0; i < TM; i++)
        #pragma unroll
        for (int j = 0; j < TN; j++) acc[i][j] = 0.f;

    for (int kk = 0; kk < K; kk += BK) {
        // ---- load A tile (BM x BK), store transposed As[k][i]
        constexpr int ELA = BM * BK / 256;   // multiple of 4 in all configs
        #pragma unroll
        for (int v = 0; v < ELA / 4; v++) {
            int idx = (t + v * 256) * 4;
            int i = idx / BK;
            int k = idx % BK;
            float4 av = *reinterpret_cast<const float4*>(&A[(size_t)(m0 + i) * lda + kk + k]);
            As[k + 0][i] = av.x; As[k + 1][i] = av.y;
            As[k + 2][i] = av.z; As[k + 3][i] = av.w;
        }
        // ---- load B tile
        constexpr int ELB = BN * BK / 256;
        if constexpr (TRANSB) {
            #pragma unroll
            for (int v = 0; v < ELB / 4; v++) {
                int idx = (t + v * 256) * 4;
                int j = idx / BK;
                int k = idx % BK;
                float4 bv = *reinterpret_cast<const float4*>(&Bm[(size_t)(n0 + j) * ldb + kk + k]);
                Bs[k + 0][j] = bv.x; Bs[k + 1][j] = bv.y;
                Bs[k + 2][j] = bv.z; Bs[k + 3][j] = bv.w;
            }
        } else {
            if constexpr (ELB % 4 == 0) {
                #pragma unroll
                for (int v = 0; v < ELB / 4; v++) {
                    int idx = (t + v * 256) * 4;
                    int k = idx / BN;
                    int j = idx % BN;
                    *reinterpret_cast<float4*>(&Bs[k][j]) =
                        *reinterpret_cast<const float4*>(&Bm[(size_t)(kk + k) * ldb + n0 + j]);
                }
            } else {
                for (int idx = t; idx < BN * BK; idx += 256) {
                    int k = idx / BN;
                    int j = idx % BN;
                    Bs[k][j] = Bm[(size_t)(kk + k) * ldb + n0 + j];
                }
            }
        }
        __syncthreads();

        #pragma unroll
        for (int k = 0; k < BK; k++) {
            float ar[TM], br[TN];
            if constexpr (TM % 4 == 0) {
                #pragma unroll
                for (int i = 0; i < TM; i += 4) {
                    float4 a4 = *reinterpret_cast<const float4*>(&As[k][ty * TM + i]);
                    ar[i] = a4.x; ar[i + 1] = a4.y; ar[i + 2] = a4.z; ar[i + 3] = a4.w;
                }
            } else {
                #pragma unroll
                for (int i = 0; i < TM; i++) ar[i] = As[k][ty * TM + i];
            }
            if constexpr (TN % 4 == 0) {
                #pragma unroll
                for (int j = 0; j < TN; j += 4) {
                    float4 b4 = *reinterpret_cast<const float4*>(&Bs[k][tx * TN + j]);
                    br[j] = b4.x; br[j + 1] = b4.y; br[j + 2] = b4.z; br[j + 3] = b4.w;
                }
            } else {
                #pragma unroll
                for (int j = 0; j < TN; j++) br[j] = Bs[k][tx * TN + j];
            }
            #pragma unroll
            for (int i = 0; i < TM; i++)
                #pragma unroll
                for (int j = 0; j < TN; j++)
                    acc[i][j] = fmaf(ar[i], br[j], acc[i][j]);
        }
        __syncthreads();
    }

    // ---- epilogue
    #pragma unroll
    for (int i = 0; i < TM; i++) {
        int row = m0 + ty * TM + i;
        #pragma unroll
        for (int j = 0; j < TN; j++) {
            int col = n0 + tx * TN + j;
            float v = acc[i][j];
            if constexpr (MODE == 0) {
                v *= scale;
                Cm[(size_t)row * ldc + col] = v;
            } else if constexpr (MODE == 1) {
                v += bias[col] + res[(size_t)row * ldres + col];
                Cm[(size_t)row * ldc + col] = v;
            } else if constexpr (MODE == 2) {
                v += bias[col];
                v = 0.5f * v * (1.0f + erff(v * 0.70710678118654752f));
                Cm[(size_t)row * ldc + col] = v;
            } else { // MODE == 3: attn@v output -> g_x[b][row][h*96+col]
                size_t off = (size_t)(bz >> 3) * ((size_t)Nn * Cc) + (size_t)(bz & 7) * HD;
                Cm[off + (size_t)row * ldc + col] = v;
            }
        }
    }
}

// ---------------------------------------------------------------------------
// Kernel 3: fused per-row softmax (all 8 heads) + re-attention head mix + BN
// One block per (b, n). In-place on g_attn.
// ---------------------------------------------------------------------------
__global__ void softmax_mix_kernel(const float* __restrict__ rw, const float* __restrict__ rb,
                                   const float* __restrict__ bng, const float* __restrict__ bnb)
{
    __shared__ float sp[8][1024];
    __shared__ float s_w[64];
    __shared__ float s_s[8], s_o[8];

    int bn = blockIdx.x;
    int b  = bn >> 10, n = bn & 1023;
    int t  = threadIdx.x;                    // 256

    if (t < 64) s_w[t] = rw[t];
    if (t < 8) {
        float bs = bng[t] * rsqrtf(1.0f + 1e-3f);
        s_s[t] = bs;
        s_o[t] = rb[t] * bs + bnb[t];
    }
    #pragma unroll
    for (int h = 0; h < 8; h++) {
        const float* rp = g_attn + (((size_t)b * Hh + h) * Nn + n) * Nn;
        for (int m = t; m < 1024; m += 256) sp[h][m] = rp[m];
    }
    __syncthreads();

    // warp w handles head w
    int w = t >> 5, lane = t & 31;
    {
        float* sr = sp[w];
        float mx = -1e30f;
        for (int m = lane; m < 1024; m += 32) mx = fmaxf(mx, sr[m]);
        #pragma unroll
        for (int off = 16; off; off >>= 1) mx = fmaxf(mx, __shfl_xor_sync(0xffffffffu, mx, off));
        float sum = 0.f;
        for (int m = lane; m < 1024; m += 32) {
            float e = __expf(sr[m] - mx);
            sr[m] = e;
            sum += e;
        }
        #pragma unroll
        for (int off = 16; off; off >>= 1) sum += __shfl_xor_sync(0xffffffffu, sum, off);
        float inv = 1.0f / sum;
        for (int m = lane; m < 1024; m += 32) sr[m] *= inv;
    }
    __syncthreads();

    for (int m = t; m < 1024; m += 256) {
        float p[8];
        #pragma unroll
        for (int h = 0; h < 8; h++) p[h] = sp[h][m];
        #pragma unroll
        for (int g = 0; g < 8; g++) {
            float a = 0.f;
            #pragma unroll
            for (int h = 0; h < 8; h++) a = fmaf(p[h], s_w[g * 8 + h], a);
            g_attn[(((size_t)b * Hh + g) * Nn + n) * Nn + m] = a * s_s[g] + s_o[g];
        }
    }
}

// ---------------------------------------------------------------------------
// LayerNorm over last dim (768). One block per row.
// ---------------------------------------------------------------------------
__global__ void layernorm_kernel(const float* __restrict__ in, float* __restrict__ out,
                                 const float* __restrict__ g, const float* __restrict__ bta)
{
    __shared__ float red[16];
    __shared__ float s_mu, s_rs;
    int row = blockIdx.x;
    int t   = threadIdx.x;       // 256
    const float* rp = in + (size_t)row * Cc;
    float x0 = rp[t], x1 = rp[t + 256], x2 = rp[t + 512];
    float s  = x0 + x1 + x2;
    float ss = x0 * x0 + x1 * x1 + x2 * x2;
    #pragma unroll
    for (int off = 16; off; off >>= 1) {
        s  += __shfl_xor_sync(0xffffffffu, s, off);
        ss += __shfl_xor_sync(0xffffffffu, ss, off);
    }
    int w = t >> 5, lane = t & 31;
    if (lane == 0) { red[w] = s; red[8 + w] = ss; }
    __syncthreads();
    if (t == 0) {
        float S = 0.f, SS = 0.f;
        #pragma unroll
        for (int i = 0; i < 8; i++) { S += red[i]; SS += red[8 + i]; }
        float mu  = S * (1.0f / 768.0f);
        float var = SS * (1.0f / 768.0f) - mu * mu;
        s_mu = mu;
        s_rs = rsqrtf(var + 1e-3f);
    }
    __syncthreads();
    float mu = s_mu, rs = s_rs;
    float* op = out + (size_t)row * Cc;
    op[t]       = (x0 - mu) * rs * g[t]       + bta[t];
    op[t + 256] = (x1 - mu) * rs * g[t + 256] + bta[t + 256];
    op[t + 512] = (x2 - mu) * rs * g[t + 512] + bta[t + 512];
}

// ---------------------------------------------------------------------------
// Launch
// ---------------------------------------------------------------------------
extern "C" void kernel_launch(void* const* d_in, const int* in_sizes, int n_in,
                              void* d_out, int out_size)
{
    (void)in_sizes; (void)n_in; (void)out_size;
    const float* enc       = (const float*)d_in[0];
    const float* qconv_w   = (const float*)d_in[1];
    const float* reatten_w = (const float*)d_in[2];
    const float* reatten_b = (const float*)d_in[3];
    const float* bn_gamma  = (const float*)d_in[4];
    const float* bn_beta   = (const float*)d_in[5];
    const float* proj_w    = (const float*)d_in[6];
    const float* proj_b    = (const float*)d_in[7];
    const float* ffn_w1    = (const float*)d_in[8];
    const float* ffn_b1    = (const float*)d_in[9];
    const float* ffn_w2    = (const float*)d_in[10];
    const float* ffn_b2    = (const float*)d_in[11];
    const float* ln1_g     = (const float*)d_in[12];
    const float* ln1_b     = (const float*)d_in[13];
    const float* ln2_g     = (const float*)d_in[14];
    const float* ln2_b     = (const float*)d_in[15];
    float* out = (float*)d_out;

    float *qp, *ap, *xp, *yp, *hp;
    cudaGetSymbolAddress((void**)&qp, g_q);
    cudaGetSymbolAddress((void**)&ap, g_attn);
    cudaGetSymbolAddress((void**)&xp, g_x);
    cudaGetSymbolAddress((void**)&yp, g_y);
    cudaGetSymbolAddress((void**)&hp, g_h);

    const float scale = 0.1020620726159658f;   // 96^-0.5

    // 1) patch conv -> g_q [b][h][n][d]
    qconv_kernel<<<NT_, 256>>>(enc, qconv_w);

    // 2) scores: S = scale * Q Q^T  (NT), per (b,h)
    gemm_kernel<128, 128, 8, 8, 8, true, 0><<<dim3(8, 8, 64), 256>>>(
        qp, qp, ap, Nn, Nn, HD, HD, HD, Nn,
        (size_t)Nn * HD, (size_t)Nn * HD, (size_t)Nn * Nn,
        nullptr, nullptr, 0, scale);

    // 3) fused softmax + head mix + BN (in-place on g_attn)
    softmax_mix_kernel<<<NT_, 256>>>(reatten_w, reatten_b, bn_gamma, bn_beta);

    // 4) O = A' V  -> g_x in [b][n][h*96+d] layout
    gemm_kernel<128, 96, 16, 8, 6, false, 3><<<dim3(1, 8, 64), 256>>>(
        ap, qp, xp, Nn, HD, Nn, Nn, HD, Cc,
        (size_t)Nn * Nn, (size_t)Nn * HD, 0,
        nullptr, nullptr, 0, 1.0f);

    // 5) proj + bias + residual(enc) -> g_y
    gemm_kernel<128, 128, 8, 8, 8, false, 1><<<dim3(6, 64, 1), 256>>>(
        xp, proj_w, yp, NT_, Cc, Cc, Cc, Cc, Cc,
        0, 0, 0, proj_b, enc, Cc, 1.0f);

    // 6) LN1 in-place on g_y
    layernorm_kernel<<<NT_, 256>>>(yp, yp, ln1_g, ln1_b);

    // 7) FFN1 + bias + exact GELU -> g_h
    gemm_kernel<128, 128, 8, 8, 8, false, 2><<<dim3(24, 64, 1), 256>>>(
        yp, ffn_w1, hp, NT_, DFF, Cc, Cc, DFF, DFF,
        0, 0, 0, ffn_b1, nullptr, 0, 1.0f);

    // 8) FFN2 + bias + residual(g_y) -> g_x
    gemm_kernel<128, 128, 8, 8, 8, false, 1><<<dim3(6, 64, 1), 256>>>(
        hp, ffn_w2, xp, NT_, Cc, DFF, DFF, Cc, Cc,
        0, 0, 0, ffn_b2, yp, Cc, 1.0f);

    // 9) LN2 -> output
    layernorm_kernel<<<NT_, 256>>>(xp, out, ln2_g, ln2_b);
}

// round 4
// speedup vs baseline: 2.5624x; 2.5624x over previous
#include <cuda_runtime.h>
#include <cuda_bf16.h>
#include <cstdint>
#include <math.h>

// Problem constants
#define Bb   8
#define Nn   1024
#define Cc   768
#define Hh   8
#define HD   96
#define DFF  3072
#define NT_  (Bb * Nn)          // 8192 tokens

// ---------------------------------------------------------------------------
// Scratch (device globals — no allocation allowed)
// ---------------------------------------------------------------------------
__device__ float g_q[(size_t)Bb * Hh * Nn * HD];          // [b][h][n][d]
__device__ float g_attn[(size_t)Bb * Hh * Nn * Nn];       // [b][h][n][m]
__device__ float g_x[(size_t)NT_ * Cc];
__device__ float g_y[(size_t)NT_ * Cc];
__device__ float g_h[(size_t)NT_ * DFF];

// ---------------------------------------------------------------------------
// helpers
// ---------------------------------------------------------------------------
__device__ __forceinline__ unsigned int f2tf(float x) {
    unsigned int r;
    asm("cvt.rna.tf32.f32 %0, %1;" : "=r"(r) : "f"(x));
    return r;
}
__device__ __forceinline__ unsigned int smem_u32(const void* p) {
    return (unsigned int)__cvta_generic_to_shared(p);
}
__device__ __forceinline__ void ldmatrix_x4(unsigned int* r, unsigned int addr) {
    asm volatile("ldmatrix.sync.aligned.m8n8.x4.shared.b16 {%0,%1,%2,%3}, [%4];"
                 : "=r"(r[0]), "=r"(r[1]), "=r"(r[2]), "=r"(r[3]) : "r"(addr));
}
__device__ __forceinline__ void ldmatrix_x2(unsigned int* r, unsigned int addr) {
    asm volatile("ldmatrix.sync.aligned.m8n8.x2.shared.b16 {%0,%1}, [%2];"
                 : "=r"(r[0]), "=r"(r[1]) : "r"(addr));
}
__device__ __forceinline__ void mma_tf32(float* c, const unsigned int* a, const unsigned int* b) {
    asm volatile(
        "mma.sync.aligned.m16n8k8.row.col.f32.tf32.tf32.f32 "
        "{%0,%1,%2,%3}, {%4,%5,%6,%7}, {%8,%9}, {%0,%1,%2,%3};"
        : "+f"(c[0]), "+f"(c[1]), "+f"(c[2]), "+f"(c[3])
        : "r"(a[0]), "r"(a[1]), "r"(a[2]), "r"(a[3]), "r"(b[0]), "r"(b[1]));
}

// ---------------------------------------------------------------------------
// Kernel 1: per-patch 3x3 conv (SAME, NHWC, HWIO), q=k=v, write [b][h][n][d]
// ---------------------------------------------------------------------------
__global__ void qconv_kernel(const float* __restrict__ x, const float* __restrict__ w)
{
    __shared__ float s_in[768];
    __shared__ float s_w[81];
    int bn = blockIdx.x;
    int b  = bn >> 10, n = bn & 1023;
    int t  = threadIdx.x;                // 256
    const float* xin = x + (size_t)bn * 768;
    s_in[t]       = xin[t];
    s_in[t + 256] = xin[t + 256];
    s_in[t + 512] = xin[t + 512];
    if (t < 81) s_w[t] = w[t];
    __syncthreads();

    int r = t >> 4, c = t & 15;
    float acc0 = 0.f, acc1 = 0.f, acc2 = 0.f;
    #pragma unroll
    for (int kh = 0; kh < 3; kh++) {
        int rr = r + kh - 1;
        if (rr < 0 || rr > 15) continue;
        #pragma unroll
        for (int kw = 0; kw < 3; kw++) {
            int cc = c + kw - 1;
            if (cc < 0 || cc > 15) continue;
            const float* wp = s_w + (kh * 3 + kw) * 9;
            int ip = (rr * 16 + cc) * 3;
            #pragma unroll
            for (int ci = 0; ci < 3; ci++) {
                float v = s_in[ip + ci];
                acc0 += v * wp[ci * 3 + 0];
                acc1 += v * wp[ci * 3 + 1];
                acc2 += v * wp[ci * 3 + 2];
            }
        }
    }
    float accs[3] = {acc0, acc1, acc2};
    #pragma unroll
    for (int co = 0; co < 3; co++) {
        int cidx = t * 3 + co;
        int h = cidx / HD, d = cidx % HD;
        g_q[(((size_t)b * Hh + h) * Nn + n) * HD + d] = accs[co];
    }
}

// ---------------------------------------------------------------------------
// TF32 tensor-core GEMM.  C = A(MxK) * op(B)  (+ fused epilogue)
//   TRANSB=true : B is (N x K) row-major (NT gemm), smem n-major + ldmatrix
//   TRANSB=false: B is (K x N) row-major (NN gemm), smem k-major + direct LDS
// MODE 0: C = acc * scale
// MODE 1: C = acc + bias[col] + res[row,col]
// MODE 2: C = gelu_exact(acc + bias[col])
// MODE 3: attention-output layout (bz=b*8+h -> g_x[b][row][h*96+col])
// Block: 256 threads = 8 warps (4 x 2). Warp tile: 32 x (BN/2).
// ---------------------------------------------------------------------------
template<int BM, int BN, int BK, bool TRANSB, int MODE>
__global__ __launch_bounds__(256, 2)
void mma_gemm(const float* __restrict__ A, const float* __restrict__ Bm,
              float* __restrict__ Cm,
              int K, int lda, int ldb, int ldc,
              size_t strideA, size_t strideB, size_t strideC,
              const float* __restrict__ bias, const float* __restrict__ res,
              int ldres, float scale)
{
    constexpr int BKP = BK + 4;              // padded stride (A smem, B-NT smem)
    constexpr int BNP = BN + 4;              // padded stride (B-NN smem)
    constexpr int WTN = BN / 2;              // warp tile N
    constexpr int MFRAG = 2;                 // 32/16
    constexpr int NFRAG = WTN / 8;           // 8 (BN=128) or 6 (BN=96)
    constexpr int BSZ = TRANSB ? (BN * BKP) : (BK * BNP);

    __shared__ unsigned int As[BM * BKP];
    __shared__ unsigned int Bs[BSZ];

    int bz = blockIdx.z;
    A  += strideA * bz;
    Bm += strideB * bz;
    if (MODE != 3) Cm += strideC * bz;

    int m0 = blockIdx.y * BM;
    int n0 = blockIdx.x * BN;
    int t    = threadIdx.x;
    int warp = t >> 5, lane = t & 31;
    int wm0 = (warp & 3) * 32;               // warp row offset in block
    int wn0 = (warp >> 2) * WTN;             // warp col offset in block

    float acc[MFRAG][NFRAG][4];
    #pragma unroll
    for (int i = 0; i < MFRAG; i++)
        #pragma unroll
        for (int j = 0; j < NFRAG; j++)
            #pragma unroll
            for (int e = 0; e < 4; e++) acc[i][j][e] = 0.f;

    // ldmatrix lane address components (A tiles: (0,0),(8,0),(0,4),(8,4))
    int a_row = ((lane >> 3) & 1) * 8 + (lane & 7);
    int a_col = (lane >> 4) * 4;
    int b_row = lane & 7;                    // for x2 (lanes 0..15 used)
    int b_col = ((lane >> 3) & 1) * 4;

    for (int kk = 0; kk < K; kk += BK) {
        // ---- A tile: BM x BK, m-major smem, convert to tf32
        #pragma unroll
        for (int v = 0; v < BM * BK / 1024; v++) {
            int idx = (t + v * 256) * 4;
            int m = idx / BK, k = idx % BK;
            float4 av = *reinterpret_cast<const float4*>(&A[(size_t)(m0 + m) * lda + kk + k]);
            unsigned int* dst = &As[m * BKP + k];
            dst[0] = f2tf(av.x); dst[1] = f2tf(av.y);
            dst[2] = f2tf(av.z); dst[3] = f2tf(av.w);
        }
        // ---- B tile
        if constexpr (TRANSB) {
            #pragma unroll
            for (int v = 0; v < BN * BK / 1024; v++) {
                int idx = (t + v * 256) * 4;
                int n = idx / BK, k = idx % BK;
                float4 bv = *reinterpret_cast<const float4*>(&Bm[(size_t)(n0 + n) * ldb + kk + k]);
                unsigned int* dst = &Bs[n * BKP + k];
                dst[0] = f2tf(bv.x); dst[1] = f2tf(bv.y);
                dst[2] = f2tf(bv.z); dst[3] = f2tf(bv.w);
            }
        } else {
            #pragma unroll
            for (int v = 0; v < BK * BN / 1024; v++) {
                int idx = (t + v * 256) * 4;
                int k = idx / BN, n = idx % BN;
                float4 bv = *reinterpret_cast<const float4*>(&Bm[(size_t)(kk + k) * ldb + n0 + n]);
                unsigned int* dst = &Bs[k * BNP + n];
                dst[0] = f2tf(bv.x); dst[1] = f2tf(bv.y);
                dst[2] = f2tf(bv.z); dst[3] = f2tf(bv.w);
            }
        }
        __syncthreads();

        #pragma unroll
        for (int ks = 0; ks < BK / 8; ks++) {
            unsigned int afr[MFRAG][4];
            #pragma unroll
            for (int mf = 0; mf < MFRAG; mf++) {
                unsigned int addr = smem_u32(&As[(wm0 + mf * 16 + a_row) * BKP + ks * 8 + a_col]);
                ldmatrix_x4(afr[mf], addr);
            }
            unsigned int bfr[NFRAG][2];
            if constexpr (TRANSB) {
                #pragma unroll
                for (int nf = 0; nf < NFRAG; nf++) {
                    unsigned int addr = smem_u32(&Bs[(wn0 + nf * 8 + b_row) * BKP + ks * 8 + b_col]);
                    ldmatrix_x2(bfr[nf], addr);
                }
            } else {
                #pragma unroll
                for (int nf = 0; nf < NFRAG; nf++) {
                    int col = wn0 + nf * 8 + (lane >> 2);
                    bfr[nf][0] = Bs[(ks * 8 + (lane & 3)) * BNP + col];
                    bfr[nf][1] = Bs[(ks * 8 + (lane & 3) + 4) * BNP + col];
                }
            }
            #pragma unroll
            for (int mf = 0; mf < MFRAG; mf++)
                #pragma unroll
                for (int nf = 0; nf < NFRAG; nf++)
                    mma_tf32(acc[mf][nf], afr[mf], bfr[nf]);
        }
        __syncthreads();
    }

    // ---- epilogue
    size_t out_off = 0;
    if constexpr (MODE == 3)
        out_off = (size_t)(bz >> 3) * ((size_t)Nn * Cc) + (size_t)(bz & 7) * HD;

    #pragma unroll
    for (int mf = 0; mf < MFRAG; mf++) {
        #pragma unroll
        for (int half = 0; half < 2; half++) {
            int row = m0 + wm0 + mf * 16 + (lane >> 2) + half * 8;
            #pragma unroll
            for (int nf = 0; nf < NFRAG; nf++) {
                int col = n0 + wn0 + nf * 8 + (lane & 3) * 2;
                float v0 = acc[mf][nf][half * 2 + 0];
                float v1 = acc[mf][nf][half * 2 + 1];
                if constexpr (MODE == 0) {
                    v0 *= scale; v1 *= scale;
                    *reinterpret_cast<float2*>(&Cm[(size_t)row * ldc + col]) = make_float2(v0, v1);
                } else if constexpr (MODE == 1) {
                    float2 bb = *reinterpret_cast<const float2*>(&bias[col]);
                    float2 rr = *reinterpret_cast<const float2*>(&res[(size_t)row * ldres + col]);
                    *reinterpret_cast<float2*>(&Cm[(size_t)row * ldc + col]) =
                        make_float2(v0 + bb.x + rr.x, v1 + bb.y + rr.y);
                } else if constexpr (MODE == 2) {
                    float2 bb = *reinterpret_cast<const float2*>(&bias[col]);
                    v0 += bb.x; v1 += bb.y;
                    v0 = 0.5f * v0 * (1.0f + erff(v0 * 0.70710678118654752f));
                    v1 = 0.5f * v1 * (1.0f + erff(v1 * 0.70710678118654752f));
                    *reinterpret_cast<float2*>(&Cm[(size_t)row * ldc + col]) = make_float2(v0, v1);
                } else {
                    *reinterpret_cast<float2*>(&Cm[out_off + (size_t)row * ldc + col]) =
                        make_float2(v0, v1);
                }
            }
        }
    }
}

// ---------------------------------------------------------------------------
// fused per-row softmax (all 8 heads) + re-attention head mix + BN
// ---------------------------------------------------------------------------
__global__ void softmax_mix_kernel(const float* __restrict__ rw, const float* __restrict__ rb,
                                   const float* __restrict__ bng, const float* __restrict__ bnb)
{
    __shared__ float sp[8][1024];
    __shared__ float s_w[64];
    __shared__ float s_s[8], s_o[8];

    int bn = blockIdx.x;
    int b  = bn >> 10, n = bn & 1023;
    int t  = threadIdx.x;                    // 256

    if (t < 64) s_w[t] = rw[t];
    if (t < 8) {
        float bs = bng[t] * rsqrtf(1.0f + 1e-3f);
        s_s[t] = bs;
        s_o[t] = rb[t] * bs + bnb[t];
    }
    #pragma unroll
    for (int h = 0; h < 8; h++) {
        const float* rp = g_attn + (((size_t)b * Hh + h) * Nn + n) * Nn;
        for (int m = t; m < 1024; m += 256) sp[h][m] = rp[m];
    }
    __syncthreads();

    int w = t >> 5, lane = t & 31;
    {
        float* sr = sp[w];
        float mx = -1e30f;
        for (int m = lane; m < 1024; m += 32) mx = fmaxf(mx, sr[m]);
        #pragma unroll
        for (int off = 16; off; off >>= 1) mx = fmaxf(mx, __shfl_xor_sync(0xffffffffu, mx, off));
        float sum = 0.f;
        for (int m = lane; m < 1024; m += 32) {
            float e = __expf(sr[m] - mx);
            sr[m] = e;
            sum += e;
        }
        #pragma unroll
        for (int off = 16; off; off >>= 1) sum += __shfl_xor_sync(0xffffffffu, sum, off);
        float inv = 1.0f / sum;
        for (int m = lane; m < 1024; m += 32) sr[m] *= inv;
    }
    __syncthreads();

    for (int m = t; m < 1024; m += 256) {
        float p[8];
        #pragma unroll
        for (int h = 0; h < 8; h++) p[h] = sp[h][m];
        #pragma unroll
        for (int g = 0; g < 8; g++) {
            float a = 0.f;
            #pragma unroll
            for (int h = 0; h < 8; h++) a = fmaf(p[h], s_w[g * 8 + h], a);
            g_attn[(((size_t)b * Hh + g) * Nn + n) * Nn + m] = a * s_s[g] + s_o[g];
        }
    }
}

// ---------------------------------------------------------------------------
// LayerNorm over last dim (768). One block per row.
// ---------------------------------------------------------------------------
__global__ void layernorm_kernel(const float* __restrict__ in, float* __restrict__ out,
                                 const float* __restrict__ g, const float* __restrict__ bta)
{
    __shared__ float red[16];
    __shared__ float s_mu, s_rs;
    int row = blockIdx.x;
    int t   = threadIdx.x;       // 256
    const float* rp = in + (size_t)row * Cc;
    float x0 = rp[t], x1 = rp[t + 256], x2 = rp[t + 512];
    float s  = x0 + x1 + x2;
    float ss = x0 * x0 + x1 * x1 + x2 * x2;
    #pragma unroll
    for (int off = 16; off; off >>= 1) {
        s  += __shfl_xor_sync(0xffffffffu, s, off);
        ss += __shfl_xor_sync(0xffffffffu, ss, off);
    }
    int w = t >> 5, lane = t & 31;
    if (lane == 0) { red[w] = s; red[8 + w] = ss; }
    __syncthreads();
    if (t == 0) {
        float S = 0.f, SS = 0.f;
        #pragma unroll
        for (int i = 0; i < 8; i++) { S += red[i]; SS += red[8 + i]; }
        float mu  = S * (1.0f / 768.0f);
        float var = SS * (1.0f / 768.0f) - mu * mu;
        s_mu = mu;
        s_rs = rsqrtf(var + 1e-3f);
    }
    __syncthreads();
    float mu = s_mu, rs = s_rs;
    float* op = out + (size_t)row * Cc;
    op[t]       = (x0 - mu) * rs * g[t]       + bta[t];
    op[t + 256] = (x1 - mu) * rs * g[t + 256] + bta[t + 256];
    op[t + 512] = (x2 - mu) * rs * g[t + 512] + bta[t + 512];
}

// ---------------------------------------------------------------------------
// Host-side launch helpers (plain C++ context for template-kernel launches)
// ---------------------------------------------------------------------------
static void launch_scores(const float* qp, float* ap, float scale)
{
    mma_gemm<128, 128, 32, true, 0><<<dim3(8, 8, 64), 256>>>(
        qp, qp, ap, HD, HD, HD, Nn,
        (size_t)Nn * HD, (size_t)Nn * HD, (size_t)Nn * Nn,
        nullptr, nullptr, 0, scale);
}
static void launch_av(const float* ap, const float* qp, float* xp)
{
    mma_gemm<128, 96, 32, false, 3><<<dim3(1, 8, 64), 256>>>(
        ap, qp, xp, Nn, Nn, HD, Cc,
        (size_t)Nn * Nn, (size_t)Nn * HD, 0,
        nullptr, nullptr, 0, 1.0f);
}
static void launch_proj(const float* xp, const float* w, float* yp,
                        const float* b, const float* res)
{
    mma_gemm<128, 128, 32, false, 1><<<dim3(6, 64, 1), 256>>>(
        xp, w, yp, Cc, Cc, Cc, Cc,
        0, 0, 0, b, res, Cc, 1.0f);
}
static void launch_ffn1(const float* yp, const float* w, float* hp, const float* b)
{
    mma_gemm<128, 128, 32, false, 2><<<dim3(24, 64, 1), 256>>>(
        yp, w, hp, Cc, Cc, DFF, DFF,
        0, 0, 0, b, nullptr, 0, 1.0f);
}
static void launch_ffn2(const float* hp, const float* w, float* xp,
                        const float* b, const float* res)
{
    mma_gemm<128, 128, 32, false, 1><<<dim3(6, 64, 1), 256>>>(
        hp, w, xp, DFF, DFF, Cc, Cc,
        0, 0, 0, b, res, Cc, 1.0f);
}

// ---------------------------------------------------------------------------
// Launch
// ---------------------------------------------------------------------------
extern "C" void kernel_launch(void* const* d_in, const int* in_sizes, int n_in,
                              void* d_out, int out_size)
{
    (void)in_sizes; (void)n_in; (void)out_size;
    const float* enc       = (const float*)d_in[0];
    const float* qconv_w   = (const float*)d_in[1];
    const float* reatten_w = (const float*)d_in[2];
    const float* reatten_b = (const float*)d_in[3];
    const float* bn_gamma  = (const float*)d_in[4];
    const float* bn_beta   = (const float*)d_in[5];
    const float* proj_w    = (const float*)d_in[6];
    const float* proj_b    = (const float*)d_in[7];
    const float* ffn_w1    = (const float*)d_in[8];
    const float* ffn_b1    = (const float*)d_in[9];
    const float* ffn_w2    = (const float*)d_in[10];
    const float* ffn_b2    = (const float*)d_in[11];
    const float* ln1_g     = (const float*)d_in[12];
    const float* ln1_b     = (const float*)d_in[13];
    const float* ln2_g     = (const float*)d_in[14];
    const float* ln2_b     = (const float*)d_in[15];
    float* out = (float*)d_out;

    float *qp, *ap, *xp, *yp, *hp;
    cudaGetSymbolAddress((void**)&qp, g_q);
    cudaGetSymbolAddress((void**)&ap, g_attn);
    cudaGetSymbolAddress((void**)&xp, g_x);
    cudaGetSymbolAddress((void**)&yp, g_y);
    cudaGetSymbolAddress((void**)&hp, g_h);

    const float scale = 0.1020620726159658f;   // 96^-0.5

    qconv_kernel<<<NT_, 256>>>(enc, qconv_w);
    launch_scores(qp, ap, scale);
    softmax_mix_kernel<<<NT_, 256>>>(reatten_w, reatten_b, bn_gamma, bn_beta);
    launch_av(ap, qp, xp);
    launch_proj(xp, proj_w, yp, proj_b, enc);
    layernorm_kernel<<<NT_, 256>>>(yp, yp, ln1_g, ln1_b);
    launch_ffn1(yp, ffn_w1, hp, ffn_b1);
    launch_ffn2(hp, ffn_w2, xp, ffn_b2, yp);
    layernorm_kernel<<<NT_, 256>>>(xp, out, ln2_g, ln2_b);
}

// round 5
// speedup vs baseline: 3.9340x; 1.5352x over previous
#include <cuda_runtime.h>
#include <cuda_bf16.h>
#include <cstdint>
#include <math.h>

// Problem constants
#define Bb   8
#define Nn   1024
#define Cc   768
#define Hh   8
#define HD   96
#define DFF  3072
#define NT_  (Bb * Nn)          // 8192 tokens

// ---------------------------------------------------------------------------
// Scratch (device globals — no allocation allowed)
// ---------------------------------------------------------------------------
__device__ float g_q[(size_t)Bb * Hh * Nn * HD];          // [b][h][n][d]
__device__ float g_attn[(size_t)Bb * Hh * Nn * Nn];       // [b][h][n][m]
__device__ float g_x[(size_t)NT_ * Cc];
__device__ float g_y[(size_t)NT_ * Cc];
__device__ float g_h[(size_t)NT_ * DFF];

// ---------------------------------------------------------------------------
// helpers
// ---------------------------------------------------------------------------
__device__ __forceinline__ unsigned int smem_u32(const void* p) {
    return (unsigned int)__cvta_generic_to_shared(p);
}
__device__ __forceinline__ void cp_async16(unsigned int dst, const void* src) {
    asm volatile("cp.async.ca.shared.global [%0], [%1], 16;\n" :: "r"(dst), "l"(src));
}
__device__ __forceinline__ void cp_commit() {
    asm volatile("cp.async.commit_group;\n");
}
template<int N>
__device__ __forceinline__ void cp_wait() {
    asm volatile("cp.async.wait_group %0;\n" :: "n"(N));
}
__device__ __forceinline__ void ldmatrix_x4(unsigned int* r, unsigned int addr) {
    asm volatile("ldmatrix.sync.aligned.m8n8.x4.shared.b16 {%0,%1,%2,%3}, [%4];"
                 : "=r"(r[0]), "=r"(r[1]), "=r"(r[2]), "=r"(r[3]) : "r"(addr));
}
__device__ __forceinline__ void ldmatrix_x2(unsigned int* r, unsigned int addr) {
    asm volatile("ldmatrix.sync.aligned.m8n8.x2.shared.b16 {%0,%1}, [%2];"
                 : "=r"(r[0]), "=r"(r[1]) : "r"(addr));
}
__device__ __forceinline__ void mma_tf32(float* c, const unsigned int* a, const unsigned int* b) {
    asm volatile(
        "mma.sync.aligned.m16n8k8.row.col.f32.tf32.tf32.f32 "
        "{%0,%1,%2,%3}, {%4,%5,%6,%7}, {%8,%9}, {%0,%1,%2,%3};"
        : "+f"(c[0]), "+f"(c[1]), "+f"(c[2]), "+f"(c[3])
        : "r"(a[0]), "r"(a[1]), "r"(a[2]), "r"(a[3]), "r"(b[0]), "r"(b[1]));
}

// ---------------------------------------------------------------------------
// Kernel 1: per-patch 3x3 conv (SAME, NHWC, HWIO), q=k=v, write [b][h][n][d]
// ---------------------------------------------------------------------------
__global__ void qconv_kernel(const float* __restrict__ x, const float* __restrict__ w)
{
    __shared__ float s_in[768];
    __shared__ float s_w[81];
    int bn = blockIdx.x;
    int b  = bn >> 10, n = bn & 1023;
    int t  = threadIdx.x;                // 256
    const float* xin = x + (size_t)bn * 768;
    s_in[t]       = xin[t];
    s_in[t + 256] = xin[t + 256];
    s_in[t + 512] = xin[t + 512];
    if (t < 81) s_w[t] = w[t];
    __syncthreads();

    int r = t >> 4, c = t & 15;
    float acc0 = 0.f, acc1 = 0.f, acc2 = 0.f;
    #pragma unroll
    for (int kh = 0; kh < 3; kh++) {
        int rr = r + kh - 1;
        if (rr < 0 || rr > 15) continue;
        #pragma unroll
        for (int kw = 0; kw < 3; kw++) {
            int cc = c + kw - 1;
            if (cc < 0 || cc > 15) continue;
            const float* wp = s_w + (kh * 3 + kw) * 9;
            int ip = (rr * 16 + cc) * 3;
            #pragma unroll
            for (int ci = 0; ci < 3; ci++) {
                float v = s_in[ip + ci];
                acc0 += v * wp[ci * 3 + 0];
                acc1 += v * wp[ci * 3 + 1];
                acc2 += v * wp[ci * 3 + 2];
            }
        }
    }
    float accs[3] = {acc0, acc1, acc2};
    #pragma unroll
    for (int co = 0; co < 3; co++) {
        int cidx = t * 3 + co;
        int h = cidx / HD, d = cidx % HD;
        g_q[(((size_t)b * Hh + h) * Nn + n) * HD + d] = accs[co];
    }
}

// ---------------------------------------------------------------------------
// TF32 tensor-core GEMM, cp.async double-buffered.
//   C = A(MxK) * op(B) (+ fused epilogue). Raw fp32 bits -> tf32 mma.
// MODE 0: C = acc*scale  | 1: acc+bias+res | 2: gelu(acc+bias) | 3: attn layout
// Block: 256 threads = 8 warps (4 x 2). Warp tile: 32 x (BN/2).
// Dynamic smem: 2 stages of (A: BM x BKP, B: NT? BN x BKP : BK x BNP).
// ---------------------------------------------------------------------------
template<int BM, int BN, int BK, bool TRANSB, int MODE>
__global__ __launch_bounds__(256, 2)
void mma_gemm(const float* __restrict__ A, const float* __restrict__ Bm,
              float* __restrict__ Cm,
              int K, int lda, int ldb, int ldc,
              size_t strideA, size_t strideB, size_t strideC,
              const float* __restrict__ bias, const float* __restrict__ res,
              int ldres, float scale)
{
    constexpr int BKP = BK + 4;
    constexpr int BNP = BN + 4;
    constexpr int WTN = BN / 2;
    constexpr int MFRAG = 2;
    constexpr int NFRAG = WTN / 8;
    constexpr int ASZ = BM * BKP;
    constexpr int BSZ = TRANSB ? (BN * BKP) : (BK * BNP);

    extern __shared__ float smem_dyn[];
    float* As = smem_dyn;                 // [2][ASZ]
    float* Bs = smem_dyn + 2 * ASZ;       // [2][BSZ]

    int bz = blockIdx.z;
    A  += strideA * bz;
    Bm += strideB * bz;
    if (MODE != 3) Cm += strideC * bz;

    int m0 = blockIdx.y * BM;
    int n0 = blockIdx.x * BN;
    int t    = threadIdx.x;
    int warp = t >> 5, lane = t & 31;
    int wm0 = (warp & 3) * 32;
    int wn0 = (warp >> 2) * WTN;

    float acc[MFRAG][NFRAG][4];
    #pragma unroll
    for (int i = 0; i < MFRAG; i++)
        #pragma unroll
        for (int j = 0; j < NFRAG; j++)
            #pragma unroll
            for (int e = 0; e < 4; e++) acc[i][j][e] = 0.f;

    int a_row = ((lane >> 3) & 1) * 8 + (lane & 7);
    int a_col = (lane >> 4) * 4;
    int b_row = lane & 7;
    int b_col = ((lane >> 3) & 1) * 4;

    // stage loader: issues cp.async for A and B tiles at k-offset kk into stage st
    auto load_stage = [&](int st, int kk) {
        float* Asd = As + st * ASZ;
        float* Bsd = Bs + st * BSZ;
        #pragma unroll
        for (int v = 0; v < BM * BK / 1024; v++) {
            int idx = (t + v * 256) * 4;
            int m = idx / BK, k = idx % BK;
            cp_async16(smem_u32(&Asd[m * BKP + k]),
                       &A[(size_t)(m0 + m) * lda + kk + k]);
        }
        if constexpr (TRANSB) {
            #pragma unroll
            for (int v = 0; v < BN * BK / 1024; v++) {
                int idx = (t + v * 256) * 4;
                int n = idx / BK, k = idx % BK;
                cp_async16(smem_u32(&Bsd[n * BKP + k]),
                           &Bm[(size_t)(n0 + n) * ldb + kk + k]);
            }
        } else {
            #pragma unroll
            for (int v = 0; v < BK * BN / 1024; v++) {
                int idx = (t + v * 256) * 4;
                int k = idx / BN, n = idx % BN;
                cp_async16(smem_u32(&Bsd[k * BNP + n]),
                           &Bm[(size_t)(kk + k) * ldb + n0 + n]);
            }
        }
    };

    int nIter = K / BK;
    load_stage(0, 0);
    cp_commit();

    for (int it = 0; it < nIter; ++it) {
        int s = it & 1;
        if (it + 1 < nIter) {
            load_stage(s ^ 1, (it + 1) * BK);
            cp_commit();
            cp_wait<1>();
        } else {
            cp_wait<0>();
        }
        __syncthreads();

        float* Asd = As + s * ASZ;
        float* Bsd = Bs + s * BSZ;
        #pragma unroll
        for (int ks = 0; ks < BK / 8; ks++) {
            unsigned int afr[MFRAG][4];
            #pragma unroll
            for (int mf = 0; mf < MFRAG; mf++) {
                unsigned int addr = smem_u32(&Asd[(wm0 + mf * 16 + a_row) * BKP + ks * 8 + a_col]);
                ldmatrix_x4(afr[mf], addr);
            }
            unsigned int bfr[NFRAG][2];
            if constexpr (TRANSB) {
                #pragma unroll
                for (int nf = 0; nf < NFRAG; nf++) {
                    unsigned int addr = smem_u32(&Bsd[(wn0 + nf * 8 + b_row) * BKP + ks * 8 + b_col]);
                    ldmatrix_x2(bfr[nf], addr);
                }
            } else {
                #pragma unroll
                for (int nf = 0; nf < NFRAG; nf++) {
                    int col = wn0 + nf * 8 + (lane >> 2);
                    bfr[nf][0] = __float_as_uint(Bsd[(ks * 8 + (lane & 3)) * BNP + col]);
                    bfr[nf][1] = __float_as_uint(Bsd[(ks * 8 + (lane & 3) + 4) * BNP + col]);
                }
            }
            #pragma unroll
            for (int mf = 0; mf < MFRAG; mf++)
                #pragma unroll
                for (int nf = 0; nf < NFRAG; nf++)
                    mma_tf32(acc[mf][nf], afr[mf], bfr[nf]);
        }
        __syncthreads();
    }

    // ---- epilogue
    size_t out_off = 0;
    if constexpr (MODE == 3)
        out_off = (size_t)(bz >> 3) * ((size_t)Nn * Cc) + (size_t)(bz & 7) * HD;

    #pragma unroll
    for (int mf = 0; mf < MFRAG; mf++) {
        #pragma unroll
        for (int half = 0; half < 2; half++) {
            int row = m0 + wm0 + mf * 16 + (lane >> 2) + half * 8;
            #pragma unroll
            for (int nf = 0; nf < NFRAG; nf++) {
                int col = n0 + wn0 + nf * 8 + (lane & 3) * 2;
                float v0 = acc[mf][nf][half * 2 + 0];
                float v1 = acc[mf][nf][half * 2 + 1];
                if constexpr (MODE == 0) {
                    v0 *= scale; v1 *= scale;
                    *reinterpret_cast<float2*>(&Cm[(size_t)row * ldc + col]) = make_float2(v0, v1);
                } else if constexpr (MODE == 1) {
                    float2 bb = *reinterpret_cast<const float2*>(&bias[col]);
                    float2 rr = *reinterpret_cast<const float2*>(&res[(size_t)row * ldres + col]);
                    *reinterpret_cast<float2*>(&Cm[(size_t)row * ldc + col]) =
                        make_float2(v0 + bb.x + rr.x, v1 + bb.y + rr.y);
                } else if constexpr (MODE == 2) {
                    float2 bb = *reinterpret_cast<const float2*>(&bias[col]);
                    v0 += bb.x; v1 += bb.y;
                    v0 = 0.5f * v0 * (1.0f + erff(v0 * 0.70710678118654752f));
                    v1 = 0.5f * v1 * (1.0f + erff(v1 * 0.70710678118654752f));
                    *reinterpret_cast<float2*>(&Cm[(size_t)row * ldc + col]) = make_float2(v0, v1);
                } else {
                    *reinterpret_cast<float2*>(&Cm[out_off + (size_t)row * ldc + col]) =
                        make_float2(v0, v1);
                }
            }
        }
    }
}

// ---------------------------------------------------------------------------
// fused per-row softmax (all 8 heads) + re-attention head mix + BN (float4 I/O)
// ---------------------------------------------------------------------------
__global__ void softmax_mix_kernel(const float* __restrict__ rw, const float* __restrict__ rb,
                                   const float* __restrict__ bng, const float* __restrict__ bnb)
{
    __shared__ __align__(16) float sp[8][1024];
    __shared__ float s_w[64];
    __shared__ float s_s[8], s_o[8];

    int bn = blockIdx.x;
    int b  = bn >> 10, n = bn & 1023;
    int t  = threadIdx.x;                    // 256

    if (t < 64) s_w[t] = rw[t];
    if (t < 8) {
        float bs = bng[t] * rsqrtf(1.0f + 1e-3f);
        s_s[t] = bs;
        s_o[t] = rb[t] * bs + bnb[t];
    }
    #pragma unroll
    for (int h = 0; h < 8; h++) {
        const float4* rp4 = reinterpret_cast<const float4*>(
            g_attn + (((size_t)b * Hh + h) * Nn + n) * Nn);
        reinterpret_cast<float4*>(sp[h])[t] = rp4[t];
    }
    __syncthreads();

    int w = t >> 5, lane = t & 31;
    {
        float* sr = sp[w];
        float mx = -1e30f;
        for (int m = lane; m < 1024; m += 32) mx = fmaxf(mx, sr[m]);
        #pragma unroll
        for (int off = 16; off; off >>= 1) mx = fmaxf(mx, __shfl_xor_sync(0xffffffffu, mx, off));
        float sum = 0.f;
        for (int m = lane; m < 1024; m += 32) {
            float e = __expf(sr[m] - mx);
            sr[m] = e;
            sum += e;
        }
        #pragma unroll
        for (int off = 16; off; off >>= 1) sum += __shfl_xor_sync(0xffffffffu, sum, off);
        float inv = 1.0f / sum;
        for (int m = lane; m < 1024; m += 32) sr[m] *= inv;
    }
    __syncthreads();

    // mix: each thread owns one float4 column chunk (m = 4t .. 4t+3)
    float4 p[8];
    #pragma unroll
    for (int h = 0; h < 8; h++) p[h] = reinterpret_cast<const float4*>(sp[h])[t];
    #pragma unroll
    for (int g = 0; g < 8; g++) {
        float4 a = make_float4(0.f, 0.f, 0.f, 0.f);
        #pragma unroll
        for (int h = 0; h < 8; h++) {
            float wgh = s_w[g * 8 + h];
            a.x = fmaf(p[h].x, wgh, a.x);
            a.y = fmaf(p[h].y, wgh, a.y);
            a.z = fmaf(p[h].z, wgh, a.z);
            a.w = fmaf(p[h].w, wgh, a.w);
        }
        float ss = s_s[g], oo = s_o[g];
        a.x = a.x * ss + oo; a.y = a.y * ss + oo;
        a.z = a.z * ss + oo; a.w = a.w * ss + oo;
        reinterpret_cast<float4*>(
            g_attn + (((size_t)b * Hh + g) * Nn + n) * Nn)[t] = a;
    }
}

// ---------------------------------------------------------------------------
// LayerNorm over last dim (768). One block per row.
// ---------------------------------------------------------------------------
__global__ void layernorm_kernel(const float* __restrict__ in, float* __restrict__ out,
                                 const float* __restrict__ g, const float* __restrict__ bta)
{
    __shared__ float red[16];
    __shared__ float s_mu, s_rs;
    int row = blockIdx.x;
    int t   = threadIdx.x;       // 256
    const float* rp = in + (size_t)row * Cc;
    float x0 = rp[t], x1 = rp[t + 256], x2 = rp[t + 512];
    float s  = x0 + x1 + x2;
    float ss = x0 * x0 + x1 * x1 + x2 * x2;
    #pragma unroll
    for (int off = 16; off; off >>= 1) {
        s  += __shfl_xor_sync(0xffffffffu, s, off);
        ss += __shfl_xor_sync(0xffffffffu, ss, off);
    }
    int w = t >> 5, lane = t & 31;
    if (lane == 0) { red[w] = s; red[8 + w] = ss; }
    __syncthreads();
    if (t == 0) {
        float S = 0.f, SS = 0.f;
        #pragma unroll
        for (int i = 0; i < 8; i++) { S += red[i]; SS += red[8 + i]; }
        float mu  = S * (1.0f / 768.0f);
        float var = SS * (1.0f / 768.0f) - mu * mu;
        s_mu = mu;
        s_rs = rsqrtf(var + 1e-3f);
    }
    __syncthreads();
    float mu = s_mu, rs = s_rs;
    float* op = out + (size_t)row * Cc;
    op[t]       = (x0 - mu) * rs * g[t]       + bta[t];
    op[t + 256] = (x1 - mu) * rs * g[t + 256] + bta[t + 256];
    op[t + 512] = (x2 - mu) * rs * g[t + 512] + bta[t + 512];
}

// ---------------------------------------------------------------------------
// Host-side launch helpers
// ---------------------------------------------------------------------------
static int smem_bytes(int BM, int BN, int BK, bool transb) {
    int asz = BM * (BK + 4);
    int bsz = transb ? BN * (BK + 4) : BK * (BN + 4);
    return 2 * (asz + bsz) * 4;
}

static void launch_scores(const float* qp, float* ap, float scale)
{
    static bool init = false;
    int sm = smem_bytes(128, 128, 32, true);
    if (!init) {
        cudaFuncSetAttribute((const void*)mma_gemm<128, 128, 32, true, 0>,
                             cudaFuncAttributeMaxDynamicSharedMemorySize, sm);
        init = true;
    }
    mma_gemm<128, 128, 32, true, 0><<<dim3(8, 8, 64), 256, sm>>>(
        qp, qp, ap, HD, HD, HD, Nn,
        (size_t)Nn * HD, (size_t)Nn * HD, (size_t)Nn * Nn,
        nullptr, nullptr, 0, scale);
}
static void launch_av(const float* ap, const float* qp, float* xp)
{
    static bool init = false;
    int sm = smem_bytes(128, 96, 32, false);
    if (!init) {
        cudaFuncSetAttribute((const void*)mma_gemm<128, 96, 32, false, 3>,
                             cudaFuncAttributeMaxDynamicSharedMemorySize, sm);
        init = true;
    }
    mma_gemm<128, 96, 32, false, 3><<<dim3(1, 8, 64), 256, sm>>>(
        ap, qp, xp, Nn, Nn, HD, Cc,
        (size_t)Nn * Nn, (size_t)Nn * HD, 0,
        nullptr, nullptr, 0, 1.0f);
}
static void launch_proj(const float* xp, const float* w, float* yp,
                        const float* b, const float* res)
{
    static bool init = false;
    int sm = smem_bytes(128, 128, 32, false);
    if (!init) {
        cudaFuncSetAttribute((const void*)mma_gemm<128, 128, 32, false, 1>,
                             cudaFuncAttributeMaxDynamicSharedMemorySize, sm);
        init = true;
    }
    mma_gemm<128, 128, 32, false, 1><<<dim3(6, 64, 1), 256, sm>>>(
        xp, w, yp, Cc, Cc, Cc, Cc,
        0, 0, 0, b, res, Cc, 1.0f);
}
static void launch_ffn1(const float* yp, const float* w, float* hp, const float* b)
{
    static bool init = false;
    int sm = smem_bytes(128, 128, 32, false);
    if (!init) {
        cudaFuncSetAttribute((const void*)mma_gemm<128, 128, 32, false, 2>,
                             cudaFuncAttributeMaxDynamicSharedMemorySize, sm);
        init = true;
    }
    mma_gemm<128, 128, 32, false, 2><<<dim3(24, 64, 1), 256, sm>>>(
        yp, w, hp, Cc, Cc, DFF, DFF,
        0, 0, 0, b, nullptr, 0, 1.0f);
}
static void launch_ffn2(const float* hp, const float* w, float* xp,
                        const float* b, const float* res)
{
    static bool init = false;
    int sm = smem_bytes(128, 128, 32, false);
    if (!init) {
        cudaFuncSetAttribute((const void*)mma_gemm<128, 128, 32, false, 1>,
                             cudaFuncAttributeMaxDynamicSharedMemorySize, sm);
        init = true;
    }
    mma_gemm<128, 128, 32, false, 1><<<dim3(6, 64, 1), 256, sm>>>(
        hp, w, xp, DFF, DFF, Cc, Cc,
        0, 0, 0, b, res, Cc, 1.0f);
}

// ---------------------------------------------------------------------------
// Launch
// ---------------------------------------------------------------------------
extern "C" void kernel_launch(void* const* d_in, const int* in_sizes, int n_in,
                              void* d_out, int out_size)
{
    (void)in_sizes; (void)n_in; (void)out_size;
    const float* enc       = (const float*)d_in[0];
    const float* qconv_w   = (const float*)d_in[1];
    const float* reatten_w = (const float*)d_in[2];
    const float* reatten_b = (const float*)d_in[3];
    const float* bn_gamma  = (const float*)d_in[4];
    const float* bn_beta   = (const float*)d_in[5];
    const float* proj_w    = (const float*)d_in[6];
    const float* proj_b    = (const float*)d_in[7];
    const float* ffn_w1    = (const float*)d_in[8];
    const float* ffn_b1    = (const float*)d_in[9];
    const float* ffn_w2    = (const float*)d_in[10];
    const float* ffn_b2    = (const float*)d_in[11];
    const float* ln1_g     = (const float*)d_in[12];
    const float* ln1_b     = (const float*)d_in[13];
    const float* ln2_g     = (const float*)d_in[14];
    const float* ln2_b     = (const float*)d_in[15];
    float* out = (float*)d_out;

    float *qp, *ap, *xp, *yp, *hp;
    cudaGetSymbolAddress((void**)&qp, g_q);
    cudaGetSymbolAddress((void**)&ap, g_attn);
    cudaGetSymbolAddress((void**)&xp, g_x);
    cudaGetSymbolAddress((void**)&yp, g_y);
    cudaGetSymbolAddress((void**)&hp, g_h);

    const float scale = 0.1020620726159658f;   // 96^-0.5

    qconv_kernel<<<NT_, 256>>>(enc, qconv_w);
    launch_scores(qp, ap, scale);
    softmax_mix_kernel<<<NT_, 256>>>(reatten_w, reatten_b, bn_gamma, bn_beta);
    launch_av(ap, qp, xp);
    launch_proj(xp, proj_w, yp, proj_b, enc);
    layernorm_kernel<<<NT_, 256>>>(yp, yp, ln1_g, ln1_b);
    launch_ffn1(yp, ffn_w1, hp, ffn_b1);
    launch_ffn2(hp, ffn_w2, xp, ffn_b2, yp);
    layernorm_kernel<<<NT_, 256>>>(xp, out, ln2_g, ln2_b);
}

// round 6
// speedup vs baseline: 4.6310x; 1.1772x over previous
#include <cuda_runtime.h>
#include <cuda_bf16.h>
#include <cstdint>
#include <math.h>

// Problem constants
#define Bb   8
#define Nn   1024
#define Cc   768
#define Hh   8
#define HD   96
#define DFF  3072
#define NT_  (Bb * Nn)          // 8192 tokens

// ---------------------------------------------------------------------------
// Scratch (device globals — no allocation allowed)
// ---------------------------------------------------------------------------
__device__ float g_q[(size_t)Bb * Hh * Nn * HD];          // [b][h][n][d]
__device__ float g_qt[(size_t)Bb * Hh * HD * Nn];         // [b][h][d][n]  (V^T)
__device__ float g_attn[(size_t)Bb * Hh * Nn * Nn];       // [b][h][n][m]
__device__ float g_x[(size_t)NT_ * Cc];
__device__ float g_y[(size_t)NT_ * Cc];
__device__ float g_h[(size_t)NT_ * DFF];
__device__ float g_pwt[(size_t)Cc * Cc];                  // proj_w^T  [out][in]
__device__ float g_w1t[(size_t)DFF * Cc];                 // ffn_w1^T  [3072][768]
__device__ float g_w2t[(size_t)Cc * DFF];                 // ffn_w2^T  [768][3072]

// ---------------------------------------------------------------------------
// helpers
// ---------------------------------------------------------------------------
__device__ __forceinline__ unsigned int smem_u32(const void* p) {
    return (unsigned int)__cvta_generic_to_shared(p);
}
__device__ __forceinline__ void cp_async16(unsigned int dst, const void* src) {
    asm volatile("cp.async.ca.shared.global [%0], [%1], 16;\n" :: "r"(dst), "l"(src));
}
__device__ __forceinline__ void cp_commit() {
    asm volatile("cp.async.commit_group;\n");
}
template<int N>
__device__ __forceinline__ void cp_wait() {
    asm volatile("cp.async.wait_group %0;\n" :: "n"(N));
}
__device__ __forceinline__ void ldmatrix_x4(unsigned int* r, unsigned int addr) {
    asm volatile("ldmatrix.sync.aligned.m8n8.x4.shared.b16 {%0,%1,%2,%3}, [%4];"
                 : "=r"(r[0]), "=r"(r[1]), "=r"(r[2]), "=r"(r[3]) : "r"(addr));
}
__device__ __forceinline__ void mma_tf32(float* c, const unsigned int* a, const unsigned int* b) {
    asm volatile(
        "mma.sync.aligned.m16n8k8.row.col.f32.tf32.tf32.f32 "
        "{%0,%1,%2,%3}, {%4,%5,%6,%7}, {%8,%9}, {%0,%1,%2,%3};"
        : "+f"(c[0]), "+f"(c[1]), "+f"(c[2]), "+f"(c[3])
        : "r"(a[0]), "r"(a[1]), "r"(a[2]), "r"(a[3]), "r"(b[0]), "r"(b[1]));
}

// ---------------------------------------------------------------------------
// Kernel 1: per-patch 3x3 conv (SAME, NHWC, HWIO), q=k=v, write [b][h][n][d]
// ---------------------------------------------------------------------------
__global__ void qconv_kernel(const float* __restrict__ x, const float* __restrict__ w)
{
    __shared__ float s_in[768];
    __shared__ float s_w[81];
    int bn = blockIdx.x;
    int b  = bn >> 10, n = bn & 1023;
    int t  = threadIdx.x;                // 256
    const float* xin = x + (size_t)bn * 768;
    s_in[t]       = xin[t];
    s_in[t + 256] = xin[t + 256];
    s_in[t + 512] = xin[t + 512];
    if (t < 81) s_w[t] = w[t];
    __syncthreads();

    int r = t >> 4, c = t & 15;
    float acc0 = 0.f, acc1 = 0.f, acc2 = 0.f;
    #pragma unroll
    for (int kh = 0; kh < 3; kh++) {
        int rr = r + kh - 1;
        if (rr < 0 || rr > 15) continue;
        #pragma unroll
        for (int kw = 0; kw < 3; kw++) {
            int cc = c + kw - 1;
            if (cc < 0 || cc > 15) continue;
            const float* wp = s_w + (kh * 3 + kw) * 9;
            int ip = (rr * 16 + cc) * 3;
            #pragma unroll
            for (int ci = 0; ci < 3; ci++) {
                float v = s_in[ip + ci];
                acc0 += v * wp[ci * 3 + 0];
                acc1 += v * wp[ci * 3 + 1];
                acc2 += v * wp[ci * 3 + 2];
            }
        }
    }
    float accs[3] = {acc0, acc1, acc2};
    #pragma unroll
    for (int co = 0; co < 3; co++) {
        int cidx = t * 3 + co;
        int h = cidx / HD, d = cidx % HD;
        g_q[(((size_t)b * Hh + h) * Nn + n) * HD + d] = accs[co];
    }
}

// ---------------------------------------------------------------------------
// Batched tiled transpose: in[z][R][C] -> out[z][C][R]. Block (32,8).
// R, C multiples of 32.
// ---------------------------------------------------------------------------
__global__ void transpose_kernel(const float* __restrict__ in, float* __restrict__ out,
                                 int R, int C, size_t sIn, size_t sOut)
{
    __shared__ float tile[32][33];
    int z = blockIdx.z;
    const float* ip = in + (size_t)z * sIn;
    float* op = out + (size_t)z * sOut;
    int c0 = blockIdx.x * 32, r0 = blockIdx.y * 32;
    int tx = threadIdx.x, ty = threadIdx.y;
    #pragma unroll
    for (int j = 0; j < 4; j++)
        tile[ty + 8 * j][tx] = ip[(size_t)(r0 + ty + 8 * j) * C + c0 + tx];
    __syncthreads();
    #pragma unroll
    for (int j = 0; j < 4; j++)
        op[(size_t)(c0 + ty + 8 * j) * R + r0 + tx] = tile[tx][ty + 8 * j];
}

// ---------------------------------------------------------------------------
// TF32 tensor-core GEMM (NT only: B is [N][K] row-major), cp.async 2-stage.
//   C = A(MxK) * B^T (+ fused epilogue). Raw fp32 bits -> tf32 mma.
// MODE 0: C = acc*scale  | 1: acc+bias+res | 2: gelu(acc+bias) | 3: attn layout
// Block: 256 threads = 8 warps (4 x 2). Warp tile: 32 x (BN/2).
// ---------------------------------------------------------------------------
template<int BM, int BN, int BK, int MODE>
__global__ __launch_bounds__(256, 2)
void mma_gemm(const float* __restrict__ A, const float* __restrict__ Bm,
              float* __restrict__ Cm,
              int K, int lda, int ldb, int ldc,
              size_t strideA, size_t strideB, size_t strideC,
              const float* __restrict__ bias, const float* __restrict__ res,
              int ldres, float scale)
{
    constexpr int BKP = BK + 4;
    constexpr int WTN = BN / 2;
    constexpr int MFRAG = 2;
    constexpr int NFRAG = WTN / 8;           // 8 (BN=128) or 6 (BN=96) — even
    constexpr int ASZ = BM * BKP;
    constexpr int BSZ = BN * BKP;

    extern __shared__ float smem_dyn[];
    float* As = smem_dyn;                 // [2][ASZ]
    float* Bs = smem_dyn + 2 * ASZ;       // [2][BSZ]

    int bz = blockIdx.z;
    A  += strideA * bz;
    Bm += strideB * bz;
    if (MODE != 3) Cm += strideC * bz;

    int m0 = blockIdx.y * BM;
    int n0 = blockIdx.x * BN;
    int t    = threadIdx.x;
    int warp = t >> 5, lane = t & 31;
    int wm0 = (warp & 3) * 32;
    int wn0 = (warp >> 2) * WTN;

    float acc[MFRAG][NFRAG][4];
    #pragma unroll
    for (int i = 0; i < MFRAG; i++)
        #pragma unroll
        for (int j = 0; j < NFRAG; j++)
            #pragma unroll
            for (int e = 0; e < 4; e++) acc[i][j][e] = 0.f;

    // ldmatrix lane address components
    int a_row = ((lane >> 3) & 1) * 8 + (lane & 7);      // A x4: (0,0),(8,0),(0,4),(8,4)
    int a_col = (lane >> 4) * 4;
    int bp_row = ((lane >> 4) & 1) * 8 + (lane & 7);     // B x4: (0,0),(0,4),(8,0),(8,4)
    int bp_col = ((lane >> 3) & 1) * 4;

    auto load_stage = [&](int st, int kk) {
        float* Asd = As + st * ASZ;
        float* Bsd = Bs + st * BSZ;
        #pragma unroll
        for (int v = 0; v < BM * BK / 1024; v++) {
            int idx = (t + v * 256) * 4;
            int m = idx / BK, k = idx % BK;
            cp_async16(smem_u32(&Asd[m * BKP + k]),
                       &A[(size_t)(m0 + m) * lda + kk + k]);
        }
        #pragma unroll
        for (int v = 0; v < BN * BK / 1024; v++) {
            int idx = (t + v * 256) * 4;
            int n = idx / BK, k = idx % BK;
            cp_async16(smem_u32(&Bsd[n * BKP + k]),
                       &Bm[(size_t)(n0 + n) * ldb + kk + k]);
        }
    };

    int nIter = K / BK;
    load_stage(0, 0);
    cp_commit();

    for (int it = 0; it < nIter; ++it) {
        int s = it & 1;
        if (it + 1 < nIter) {
            load_stage(s ^ 1, (it + 1) * BK);
            cp_commit();
            cp_wait<1>();
        } else {
            cp_wait<0>();
        }
        __syncthreads();

        float* Asd = As + s * ASZ;
        float* Bsd = Bs + s * BSZ;
        #pragma unroll
        for (int ks = 0; ks < BK / 8; ks++) {
            unsigned int afr[MFRAG][4];
            #pragma unroll
            for (int mf = 0; mf < MFRAG; mf++) {
                unsigned int addr = smem_u32(&Asd[(wm0 + mf * 16 + a_row) * BKP + ks * 8 + a_col]);
                ldmatrix_x4(afr[mf], addr);
            }
            unsigned int bfr[NFRAG][2];
            #pragma unroll
            for (int np = 0; np < NFRAG / 2; np++) {
                unsigned int addr = smem_u32(&Bsd[(wn0 + np * 16 + bp_row) * BKP + ks * 8 + bp_col]);
                ldmatrix_x4(&bfr[np * 2][0], addr);
            }
            #pragma unroll
            for (int mf = 0; mf < MFRAG; mf++)
                #pragma unroll
                for (int nf = 0; nf < NFRAG; nf++)
                    mma_tf32(acc[mf][nf], afr[mf], bfr[nf]);
        }
        __syncthreads();
    }

    // ---- epilogue
    size_t out_off = 0;
    if constexpr (MODE == 3)
        out_off = (size_t)(bz >> 3) * ((size_t)Nn * Cc) + (size_t)(bz & 7) * HD;

    #pragma unroll
    for (int mf = 0; mf < MFRAG; mf++) {
        #pragma unroll
        for (int half = 0; half < 2; half++) {
            int row = m0 + wm0 + mf * 16 + (lane >> 2) + half * 8;
            #pragma unroll
            for (int nf = 0; nf < NFRAG; nf++) {
                int col = n0 + wn0 + nf * 8 + (lane & 3) * 2;
                float v0 = acc[mf][nf][half * 2 + 0];
                float v1 = acc[mf][nf][half * 2 + 1];
                if constexpr (MODE == 0) {
                    v0 *= scale; v1 *= scale;
                    *reinterpret_cast<float2*>(&Cm[(size_t)row * ldc + col]) = make_float2(v0, v1);
                } else if constexpr (MODE == 1) {
                    float2 bb = *reinterpret_cast<const float2*>(&bias[col]);
                    float2 rr = *reinterpret_cast<const float2*>(&res[(size_t)row * ldres + col]);
                    *reinterpret_cast<float2*>(&Cm[(size_t)row * ldc + col]) =
                        make_float2(v0 + bb.x + rr.x, v1 + bb.y + rr.y);
                } else if constexpr (MODE == 2) {
                    float2 bb = *reinterpret_cast<const float2*>(&bias[col]);
                    v0 += bb.x; v1 += bb.y;
                    v0 = 0.5f * v0 * (1.0f + erff(v0 * 0.70710678118654752f));
                    v1 = 0.5f * v1 * (1.0f + erff(v1 * 0.70710678118654752f));
                    *reinterpret_cast<float2*>(&Cm[(size_t)row * ldc + col]) = make_float2(v0, v1);
                } else {
                    *reinterpret_cast<float2*>(&Cm[out_off + (size_t)row * ldc + col]) =
                        make_float2(v0, v1);
                }
            }
        }
    }
}

// ---------------------------------------------------------------------------
// fused per-row softmax (all 8 heads) + re-attention head mix + BN (float4 I/O)
// ---------------------------------------------------------------------------
__global__ void softmax_mix_kernel(const float* __restrict__ rw, const float* __restrict__ rb,
                                   const float* __restrict__ bng, const float* __restrict__ bnb)
{
    __shared__ __align__(16) float sp[8][1024];
    __shared__ float s_w[64];
    __shared__ float s_s[8], s_o[8];

    int bn = blockIdx.x;
    int b  = bn >> 10, n = bn & 1023;
    int t  = threadIdx.x;                    // 256

    if (t < 64) s_w[t] = rw[t];
    if (t < 8) {
        float bs = bng[t] * rsqrtf(1.0f + 1e-3f);
        s_s[t] = bs;
        s_o[t] = rb[t] * bs + bnb[t];
    }
    #pragma unroll
    for (int h = 0; h < 8; h++) {
        const float4* rp4 = reinterpret_cast<const float4*>(
            g_attn + (((size_t)b * Hh + h) * Nn + n) * Nn);
        reinterpret_cast<float4*>(sp[h])[t] = rp4[t];
    }
    __syncthreads();

    int w = t >> 5, lane = t & 31;
    {
        float* sr = sp[w];
        float mx = -1e30f;
        for (int m = lane; m < 1024; m += 32) mx = fmaxf(mx, sr[m]);
        #pragma unroll
        for (int off = 16; off; off >>= 1) mx = fmaxf(mx, __shfl_xor_sync(0xffffffffu, mx, off));
        float sum = 0.f;
        for (int m = lane; m < 1024; m += 32) {
            float e = __expf(sr[m] - mx);
            sr[m] = e;
            sum += e;
        }
        #pragma unroll
        for (int off = 16; off; off >>= 1) sum += __shfl_xor_sync(0xffffffffu, sum, off);
        float inv = 1.0f / sum;
        for (int m = lane; m < 1024; m += 32) sr[m] *= inv;
    }
    __syncthreads();

    float4 p[8];
    #pragma unroll
    for (int h = 0; h < 8; h++) p[h] = reinterpret_cast<const float4*>(sp[h])[t];
    #pragma unroll
    for (int g = 0; g < 8; g++) {
        float4 a = make_float4(0.f, 0.f, 0.f, 0.f);
        #pragma unroll
        for (int h = 0; h < 8; h++) {
            float wgh = s_w[g * 8 + h];
            a.x = fmaf(p[h].x, wgh, a.x);
            a.y = fmaf(p[h].y, wgh, a.y);
            a.z = fmaf(p[h].z, wgh, a.z);
            a.w = fmaf(p[h].w, wgh, a.w);
        }
        float ss = s_s[g], oo = s_o[g];
        a.x = a.x * ss + oo; a.y = a.y * ss + oo;
        a.z = a.z * ss + oo; a.w = a.w * ss + oo;
        reinterpret_cast<float4*>(
            g_attn + (((size_t)b * Hh + g) * Nn + n) * Nn)[t] = a;
    }
}

// ---------------------------------------------------------------------------
// LayerNorm over last dim (768). One block per row.
// ---------------------------------------------------------------------------
__global__ void layernorm_kernel(const float* __restrict__ in, float* __restrict__ out,
                                 const float* __restrict__ g, const float* __restrict__ bta)
{
    __shared__ float red[16];
    __shared__ float s_mu, s_rs;
    int row = blockIdx.x;
    int t   = threadIdx.x;       // 256
    const float* rp = in + (size_t)row * Cc;
    float x0 = rp[t], x1 = rp[t + 256], x2 = rp[t + 512];
    float s  = x0 + x1 + x2;
    float ss = x0 * x0 + x1 * x1 + x2 * x2;
    #pragma unroll
    for (int off = 16; off; off >>= 1) {
        s  += __shfl_xor_sync(0xffffffffu, s, off);
        ss += __shfl_xor_sync(0xffffffffu, ss, off);
    }
    int w = t >> 5, lane = t & 31;
    if (lane == 0) { red[w] = s; red[8 + w] = ss; }
    __syncthreads();
    if (t == 0) {
        float S = 0.f, SS = 0.f;
        #pragma unroll
        for (int i = 0; i < 8; i++) { S += red[i]; SS += red[8 + i]; }
        float mu  = S * (1.0f / 768.0f);
        float var = SS * (1.0f / 768.0f) - mu * mu;
        s_mu = mu;
        s_rs = rsqrtf(var + 1e-3f);
    }
    __syncthreads();
    float mu = s_mu, rs = s_rs;
    float* op = out + (size_t)row * Cc;
    op[t]       = (x0 - mu) * rs * g[t]       + bta[t];
    op[t + 256] = (x1 - mu) * rs * g[t + 256] + bta[t + 256];
    op[t + 512] = (x2 - mu) * rs * g[t + 512] + bta[t + 512];
}

// ---------------------------------------------------------------------------
// Host-side launch helpers
// ---------------------------------------------------------------------------
static int smem_bytes(int BM, int BN, int BK) {
    return 2 * (BM * (BK + 4) + BN * (BK + 4)) * 4;
}

static void launch_scores(const float* qp, float* ap, float scale)
{
    static bool init = false;
    int sm = smem_bytes(128, 128, 32);
    if (!init) {
        cudaFuncSetAttribute((const void*)mma_gemm<128, 128, 32, 0>,
                             cudaFuncAttributeMaxDynamicSharedMemorySize, sm);
        init = true;
    }
    mma_gemm<128, 128, 32, 0><<<dim3(8, 8, 64), 256, sm>>>(
        qp, qp, ap, HD, HD, HD, Nn,
        (size_t)Nn * HD, (size_t)Nn * HD, (size_t)Nn * Nn,
        nullptr, nullptr, 0, scale);
}
static void launch_av(const float* ap, const float* vtp, float* xp)
{
    static bool init = false;
    int sm = smem_bytes(128, 96, 32);
    if (!init) {
        cudaFuncSetAttribute((const void*)mma_gemm<128, 96, 32, 3>,
                             cudaFuncAttributeMaxDynamicSharedMemorySize, sm);
        init = true;
    }
    mma_gemm<128, 96, 32, 3><<<dim3(1, 8, 64), 256, sm>>>(
        ap, vtp, xp, Nn, Nn, Nn, Cc,
        (size_t)Nn * Nn, (size_t)Nn * HD, 0,
        nullptr, nullptr, 0, 1.0f);
}
static void launch_proj(const float* xp, const float* wt, float* yp,
                        const float* b, const float* res)
{
    static bool init = false;
    int sm = smem_bytes(128, 128, 32);
    if (!init) {
        cudaFuncSetAttribute((const void*)mma_gemm<128, 128, 32, 1>,
                             cudaFuncAttributeMaxDynamicSharedMemorySize, sm);
        init = true;
    }
    mma_gemm<128, 128, 32, 1><<<dim3(6, 64, 1), 256, sm>>>(
        xp, wt, yp, Cc, Cc, Cc, Cc,
        0, 0, 0, b, res, Cc, 1.0f);
}
static void launch_ffn1(const float* yp, const float* wt, float* hp, const float* b)
{
    static bool init = false;
    int sm = smem_bytes(128, 128, 32);
    if (!init) {
        cudaFuncSetAttribute((const void*)mma_gemm<128, 128, 32, 2>,
                             cudaFuncAttributeMaxDynamicSharedMemorySize, sm);
        init = true;
    }
    mma_gemm<128, 128, 32, 2><<<dim3(24, 64, 1), 256, sm>>>(
        yp, wt, hp, Cc, Cc, Cc, DFF,
        0, 0, 0, b, nullptr, 0, 1.0f);
}
static void launch_ffn2(const float* hp, const float* wt, float* xp,
                        const float* b, const float* res)
{
    static bool init = false;
    int sm = smem_bytes(128, 128, 32);
    if (!init) {
        cudaFuncSetAttribute((const void*)mma_gemm<128, 128, 32, 1>,
                             cudaFuncAttributeMaxDynamicSharedMemorySize, sm);
        init = true;
    }
    mma_gemm<128, 128, 32, 1><<<dim3(6, 64, 1), 256, sm>>>(
        hp, wt, xp, DFF, DFF, DFF, Cc,
        0, 0, 0, b, res, Cc, 1.0f);
}

// ---------------------------------------------------------------------------
// Launch
// ---------------------------------------------------------------------------
extern "C" void kernel_launch(void* const* d_in, const int* in_sizes, int n_in,
                              void* d_out, int out_size)
{
    (void)in_sizes; (void)n_in; (void)out_size;
    const float* enc       = (const float*)d_in[0];
    const float* qconv_w   = (const float*)d_in[1];
    const float* reatten_w = (const float*)d_in[2];
    const float* reatten_b = (const float*)d_in[3];
    const float* bn_gamma  = (const float*)d_in[4];
    const float* bn_beta   = (const float*)d_in[5];
    const float* proj_w    = (const float*)d_in[6];
    const float* proj_b    = (const float*)d_in[7];
    const float* ffn_w1    = (const float*)d_in[8];
    const float* ffn_b1    = (const float*)d_in[9];
    const float* ffn_w2    = (const float*)d_in[10];
    const float* ffn_b2    = (const float*)d_in[11];
    const float* ln1_g     = (const float*)d_in[12];
    const float* ln1_b     = (const float*)d_in[13];
    const float* ln2_g     = (const float*)d_in[14];
    const float* ln2_b     = (const float*)d_in[15];
    float* out = (float*)d_out;

    float *qp, *qtp, *ap, *xp, *yp, *hp, *pwt, *w1t, *w2t;
    cudaGetSymbolAddress((void**)&qp,  g_q);
    cudaGetSymbolAddress((void**)&qtp, g_qt);
    cudaGetSymbolAddress((void**)&ap,  g_attn);
    cudaGetSymbolAddress((void**)&xp,  g_x);
    cudaGetSymbolAddress((void**)&yp,  g_y);
    cudaGetSymbolAddress((void**)&hp,  g_h);
    cudaGetSymbolAddress((void**)&pwt, g_pwt);
    cudaGetSymbolAddress((void**)&w1t, g_w1t);
    cudaGetSymbolAddress((void**)&w2t, g_w2t);

    const float scale = 0.1020620726159658f;   // 96^-0.5

    // weight transposes ([K][N] -> [N][K])
    transpose_kernel<<<dim3(24, 24, 1), dim3(32, 8)>>>(proj_w, pwt, Cc, Cc, 0, 0);
    transpose_kernel<<<dim3(96, 24, 1), dim3(32, 8)>>>(ffn_w1, w1t, Cc, DFF, 0, 0);
    transpose_kernel<<<dim3(24, 96, 1), dim3(32, 8)>>>(ffn_w2, w2t, DFF, Cc, 0, 0);

    qconv_kernel<<<NT_, 256>>>(enc, qconv_w);
    // V^T per (b,h): [1024][96] -> [96][1024]
    transpose_kernel<<<dim3(3, 32, 64), dim3(32, 8)>>>(qp, qtp, Nn, HD,
                                                       (size_t)Nn * HD, (size_t)Nn * HD);

    launch_scores(qp, ap, scale);
    softmax_mix_kernel<<<NT_, 256>>>(reatten_w, reatten_b, bn_gamma, bn_beta);
    launch_av(ap, qtp, xp);
    launch_proj(xp, pwt, yp, proj_b, enc);
    layernorm_kernel<<<NT_, 256>>>(yp, yp, ln1_g, ln1_b);
    launch_ffn1(yp, w1t, hp, ffn_b1);
    launch_ffn2(hp, w2t, xp, ffn_b2, yp);
    layernorm_kernel<<<NT_, 256>>>(xp, out, ln2_g, ln2_b);
}